// round 17
// baseline (speedup 1.0000x reference)
#include <cuda_runtime.h>
#include <cuda_fp16.h>
#include <cstdint>

// ---------------------------------------------------------------------------
// Multi-level dense 3x3x3 conv, C_in=C_out=16, B=2, SAME zero padding.
// Tensor-core version: 27 shift-GEMMs via mma.sync.m16n8k16 (fp16 x fp16 -> fp32).
// Input planes staged in smem as fp16 [y_halo][x_halo][cin]; a voxel row is
// 32 contiguous bytes, so ldmatrix.x4 with shifted row addresses materializes
// the A-tile for any (dy,dx) offset directly (halo zeros = SAME padding).
// ---------------------------------------------------------------------------

constexpr int NLEV   = 16;
constexpr int NTOT   = 1846083;          // sum of R^3 over all levels
constexpr int XH     = 18;               // x extent with halo
constexpr int YH     = 18;               // y extent with halo
constexpr int PLANE_H = YH * XH * 16;    // halves per z-plane = 5184 (10368 B)
constexpr int WH     = 27 * 16 * 16;     // weight halves per level = 6912
constexpr int TZ     = 8;                // z-slab per block

__constant__ int c_R[NLEV]    = {16,18,20,22,25,27,30,34,38,42,47,52,58,64,72,80};
__constant__ int c_off[NLEV]  = {0,4096,9928,17928,28576,44201,63884,90884,
                                 130188,185060,259148,362971,503579,698691,
                                 960835,1334083};
// cumulative tile starts per level (tiles = 2 * ntx^2 * ntz)
__constant__ int c_ts[NLEV+1] = {0,4,28,52,76,108,140,172,262,352,460,568,
                                 792,1048,1304,1754,2254};
__constant__ int c_ntx[NLEV]  = {1,2,2,2,2,2,2,3,3,3,3,4,4,4,5,5};
__constant__ int c_ntz[NLEV]  = {2,3,3,3,4,4,4,5,5,6,6,7,8,8,9,10};

__device__ __forceinline__ uint32_t smem_u32(const void* p) {
    return (uint32_t)__cvta_generic_to_shared(p);
}

__device__ __forceinline__ void ldsm_x4(uint32_t& r0, uint32_t& r1,
                                        uint32_t& r2, uint32_t& r3, uint32_t addr) {
    asm volatile("ldmatrix.sync.aligned.m8n8.x4.shared.b16 {%0,%1,%2,%3}, [%4];\n"
                 : "=r"(r0), "=r"(r1), "=r"(r2), "=r"(r3) : "r"(addr));
}

__device__ __forceinline__ void ldsm_x4_trans(uint32_t& r0, uint32_t& r1,
                                              uint32_t& r2, uint32_t& r3, uint32_t addr) {
    asm volatile("ldmatrix.sync.aligned.m8n8.x4.trans.shared.b16 {%0,%1,%2,%3}, [%4];\n"
                 : "=r"(r0), "=r"(r1), "=r"(r2), "=r"(r3) : "r"(addr));
}

__device__ __forceinline__ void mma16816(float* d, uint32_t a0, uint32_t a1,
                                         uint32_t a2, uint32_t a3,
                                         uint32_t b0, uint32_t b1) {
    asm volatile(
        "mma.sync.aligned.m16n8k16.row.col.f32.f16.f16.f32 "
        "{%0,%1,%2,%3}, {%4,%5,%6,%7}, {%8,%9}, {%0,%1,%2,%3};\n"
        : "+f"(d[0]), "+f"(d[1]), "+f"(d[2]), "+f"(d[3])
        : "r"(a0), "r"(a1), "r"(a2), "r"(a3), "r"(b0), "r"(b1));
}

// Load global z-plane gz (with x/y halo, zero padded) into fp16 smem slot gz mod 3.
__device__ __forceinline__ void load_plane(__half* p_s, const float* __restrict__ inB,
                                           int R, int x0, int y0, int gz)
{
    __half* dst = p_s + ((gz + 3) % 3) * PLANE_H;   // gz >= -1 always
    const int tid = threadIdx.x;
    if (gz < 0 || gz >= R) {
        uint4 z4 = make_uint4(0, 0, 0, 0);
        for (int u = tid; u < PLANE_H / 8; u += 256)
            reinterpret_cast<uint4*>(dst)[u] = z4;
        return;
    }
    const float* src = inB + (size_t)gz * R * R * 16;
    for (int u = tid; u < YH * XH * 4; u += 256) {
        const int c4 = u & 3;
        const int v  = u >> 2;
        const int i  = v % XH;
        const int j  = v / XH;
        const int gx = x0 - 1 + i;
        const int gy = y0 - 1 + j;
        float4 val = make_float4(0.f, 0.f, 0.f, 0.f);
        if ((unsigned)gx < (unsigned)R && (unsigned)gy < (unsigned)R)
            val = *reinterpret_cast<const float4*>(
                      src + ((size_t)gy * R + gx) * 16 + c4 * 4);
        __half2 h01 = __floats2half2_rn(val.x, val.y);
        __half2 h23 = __floats2half2_rn(val.z, val.w);
        uint2 pk;
        pk.x = *reinterpret_cast<uint32_t*>(&h01);
        pk.y = *reinterpret_cast<uint32_t*>(&h23);
        *reinterpret_cast<uint2*>(dst + (j * XH + i) * 16 + c4 * 4) = pk;
    }
}

extern "C" __global__ void __launch_bounds__(256)
conv_all_levels(const float* __restrict__ input,
                const float* __restrict__ weight,
                const float* __restrict__ bias,
                float* __restrict__ out)
{
    __shared__ __half w_s[WH];          // fp16 weights [27][ci][co]
    __shared__ float  b_s[16];
    __shared__ __half p_s[3 * PLANE_H]; // 3 z-planes, [y_halo][x_halo][cin]

    const int tid = threadIdx.x;

    // ---- decode block -> (level, batch, tile) ----
    int l = 0;
    const int bId = blockIdx.x;
    while (bId >= c_ts[l + 1]) ++l;
    int t = bId - c_ts[l];
    const int R     = c_R[l];
    const int ntx   = c_ntx[l];
    const int ntz   = c_ntz[l];
    const int nxy   = ntx * ntx;
    const int per_b = nxy * ntz;
    const int b   = t / per_b;  t -= b * per_b;
    const int tz  = t / nxy;    t -= tz * nxy;
    const int tyi = t / ntx;
    const int txi = t - tyi * ntx;
    const int x0 = txi * 16, y0 = tyi * 16, z0 = tz * TZ;

    const float* inB  = input + ((size_t)b * NTOT + c_off[l]) * 16;
    float*       outB = out   + ((size_t)b * NTOT + c_off[l]) * 16;

    // ---- stage fp16 weights + fp32 bias ----
    const float* wg = weight + l * WH;
    for (int u = tid; u < WH; u += 256) w_s[u] = __float2half(wg[u]);
    if (tid < 16) b_s[tid] = bias[l * 16 + tid];

    // ---- preload planes z0-1, z0 ----
    load_plane(p_s, inB, R, x0, y0, z0 - 1);
    load_plane(p_s, inB, R, x0, y0, z0);
    __syncthreads();

    const int lane = tid & 31;
    const int wid  = tid >> 5;
    const int yl   = wid * 2;                       // local y of warp's first row
    // ldmatrix per-lane address component: row (l&15)*32B + k/n-half (l>>4)*16B
    const uint32_t lane_off = (uint32_t)((lane & 15) * 32 + (lane >> 4) * 16);
    const uint32_t wbase = smem_u32(w_s);
    const uint32_t pbase = smem_u32(p_s);

    const bool warp_act = (y0 + yl) < R;
    const int  zend = min(z0 + TZ, R);

    // per-thread bias pairs for the two n-halves: co = (lane&3)*2 + h*8
    const int co0 = (lane & 3) * 2;
    float2 bias_h[2];
    bias_h[0] = make_float2(b_s[co0],     b_s[co0 + 1]);
    bias_h[1] = make_float2(b_s[co0 + 8], b_s[co0 + 9]);

    for (int z = z0; z < zend; ++z) {
        load_plane(p_s, inB, R, x0, y0, z + 1);
        __syncthreads();

        float d[2][8];
        #pragma unroll
        for (int i = 0; i < 16; ++i) d[i >> 3][i & 7] = 0.f;

        if (warp_act) {
            #pragma unroll
            for (int dz = 0; dz < 3; ++dz) {
                const uint32_t pb = pbase + (uint32_t)(((z - 1 + dz + 3) % 3) * PLANE_H * 2);
                #pragma unroll
                for (int dy = 0; dy < 3; ++dy) {
                    #pragma unroll
                    for (int dx = 0; dx < 3; ++dx) {
                        const int k = dz * 9 + dy * 3 + dx;
                        uint32_t b0, b1, b2, b3;
                        ldsm_x4_trans(b0, b1, b2, b3, wbase + (uint32_t)(k * 512) + lane_off);
                        #pragma unroll
                        for (int tt = 0; tt < 2; ++tt) {
                            // A tile: rows = voxels x=0..15 at halo (yl+tt+dy, x+dx)
                            const uint32_t aaddr =
                                pb + (uint32_t)(((yl + tt + dy) * XH + dx) * 32) + lane_off;
                            uint32_t a0, a1, a2, a3;
                            ldsm_x4(a0, a1, a2, a3, aaddr);
                            mma16816(d[tt],     a0, a1, a2, a3, b0, b1);
                            mma16816(d[tt] + 4, a0, a1, a2, a3, b2, b3);
                        }
                    }
                }
            }
        }
        __syncthreads();   // protect plane slot reuse by next iteration's load

        if (warp_act) {
            const int xA = x0 + (lane >> 2);       // rows l/4 and l/4+8 of D
            const int xB = xA + 8;
            #pragma unroll
            for (int tt = 0; tt < 2; ++tt) {
                const int yg = y0 + yl + tt;
                if (yg >= R) break;
                float* orow = outB + ((size_t)z * R * R + (size_t)yg * R) * 16;
                #pragma unroll
                for (int h = 0; h < 2; ++h) {
                    const int co = co0 + h * 8;
                    if (xA < R) {
                        float2 v = make_float2(d[tt][h * 4 + 0] + bias_h[h].x,
                                               d[tt][h * 4 + 1] + bias_h[h].y);
                        *reinterpret_cast<float2*>(orow + (size_t)xA * 16 + co) = v;
                    }
                    if (xB < R) {
                        float2 v = make_float2(d[tt][h * 4 + 2] + bias_h[h].x,
                                               d[tt][h * 4 + 3] + bias_h[h].y);
                        *reinterpret_cast<float2*>(orow + (size_t)xB * 16 + co) = v;
                    }
                }
            }
        }
    }
}

extern "C" void kernel_launch(void* const* d_in, const int* in_sizes, int n_in,
                              void* d_out, int out_size)
{
    const float* input  = (const float*)d_in[0];
    const float* weight = (const float*)d_in[1];
    const float* bias   = (const float*)d_in[2];
    float* out = (float*)d_out;

    conv_all_levels<<<2254, 256>>>(input, weight, bias, out);
}